// round 8
// baseline (speedup 1.0000x reference)
#include <cuda_runtime.h>

#define IN_DIM   2048
#define OUT_DIM  14951
#define THREADS  256
#define EPS      1e-12f

__global__ __launch_bounds__(THREADS)
void hc_kernel(const float* __restrict__ x,
               const float* __restrict__ scale,
               const float* __restrict__ bias,
               float* __restrict__ out)
{
    __shared__ alignas(16) float xch[IN_DIM];   // exchange buffer, then shifted-y buffer
    __shared__ float sred[THREADS / 32];
    __shared__ float sc;

    const int t    = threadIdx.x;
    const int row  = blockIdx.x;
    const int lane = t & 31;
    const int s    = row & 3;        // alignment shift: base + j aligned iff j ≡ s (mod 4)

    // res[q] holds element n = q*256 + t of this row's transform
    float res[8];

    const float* __restrict__ xr = x + (size_t)row * IN_DIM;

    // ---- load (coalesced, evict-first: x never reused) + sum of squares ----
    float ss = 0.f;
#pragma unroll
    for (int q = 0; q < 8; ++q) {
        float v = __ldcs(xr + q * THREADS + t);
        res[q] = v;
        ss += v * v;
    }
#pragma unroll
    for (int o = 16; o; o >>= 1) ss += __shfl_xor_sync(0xFFFFFFFFu, ss, o);
    if (lane == 0) sred[t >> 5] = ss;
    __syncthreads();
    if (t == 0) {
        float tot = 0.f;
#pragma unroll
        for (int w = 0; w < THREADS / 32; ++w) tot += sred[w];
        sc = -scale[0] * rsqrtf(fmaxf(tot, EPS));
    }

    // ---- 3 register stages (bits 8..10 of n == bits of q) ----
#pragma unroll
    for (int B = 1; B < 8; B <<= 1) {
#pragma unroll
        for (int q = 0; q < 8; ++q) {
            if (!(q & B)) {
                float a0 = res[q], a1 = res[q | B];
                res[q]     = a0 + a1;
                res[q | B] = a0 - a1;
            }
        }
    }

    // ---- 5 shuffle stages (bits 0..4 of n == lane bits of t) ----
#pragma unroll
    for (int h = 1; h <= 16; h <<= 1) {
#pragma unroll
        for (int q = 0; q < 8; ++q) {
            float o = __shfl_xor_sync(0xFFFFFFFFu, res[q], h);
            res[q] = (t & h) ? (o - res[q]) : (res[q] + o);
        }
    }

    // ---- 3 smem exchange stages (bits 5..7 of n == warp bits of t) ----
#pragma unroll
    for (int h = 32; h <= 128; h <<= 1) {
        __syncthreads();
#pragma unroll
        for (int q = 0; q < 8; ++q) xch[q * THREADS + t] = res[q];
        __syncthreads();
#pragma unroll
        for (int q = 0; q < 8; ++q) {
            float o = xch[q * THREADS + (t ^ h)];
            res[q] = (t & h) ? (o - res[q]) : (res[q] + o);
        }
    }

    // ---- write SHIFTED y to smem: xch[k] = y[(k+s) & 2047] ----
    // (res[q] = y[q*256 + t]; write at k = (q*256 + t - s) mod 2048; stride-1 per warp)
    __syncthreads();
#pragma unroll
    for (int q = 0; q < 8; ++q) {
        int k = (q * THREADS + t - s) & (IN_DIM - 1);
        xch[k] = res[q];
    }
    __syncthreads();

    const float c = sc;
    float* __restrict__ orow = out + (size_t)row * OUT_DIM;

    // ---- head: j = 0..s-1 (scalar, <=3 elems) ----
    if (t < s) {
        int j = t;
        float yv = xch[(j - s) & (IN_DIM - 1)];
        __stcs(orow + j, fmaf(c, yv, __ldg(bias + j)));
    }
    // ---- tail: j = s+14948 .. 14950 (scalar, <=3 elems) ----
    if (t < 3 - s) {
        int j = s + 14948 + t;
        float yv = xch[(14948 + t) & (IN_DIM - 1)];
        __stcs(orow + j, fmaf(c, yv, __ldg(bias + j)));
    }

    // ---- body: 3737 aligned float4 chunks; j = s + 4i, global index 16B-aligned ----
    // rolled loop, chunk order rotated by row (decorrelates bias-line contention)
    const int NB  = (OUT_DIM - s) >> 2;        // 3737 for all s
    int it0 = row % 15;
#pragma unroll 1
    for (int cc = 0; cc < 15; ++cc) {
        int it = it0 + cc;
        if (it >= 15) it -= 15;
        int i = t + (it << 8);
        if (i < NB) {
            int k = i << 2;                                        // aligned, = j - s
            float4 yv = *reinterpret_cast<const float4*>(xch + (k & (IN_DIM - 1)));
            int j = k + s;
            float b0 = __ldg(bias + j);
            float b1 = __ldg(bias + j + 1);
            float b2 = __ldg(bias + j + 2);
            float b3 = __ldg(bias + j + 3);
            float4 o4 = make_float4(fmaf(c, yv.x, b0), fmaf(c, yv.y, b1),
                                    fmaf(c, yv.z, b2), fmaf(c, yv.w, b3));
            __stcs(reinterpret_cast<float4*>(orow + j), o4);
        }
    }
}

extern "C" void kernel_launch(void* const* d_in, const int* in_sizes, int n_in,
                              void* d_out, int out_size)
{
    const float* x     = (const float*)d_in[0];
    const float* scale = (const float*)d_in[1];
    const float* bias  = (const float*)d_in[2];
    float* out = (float*)d_out;

    const int batch = in_sizes[0] / IN_DIM;     // 4096
    hc_kernel<<<batch, THREADS>>>(x, scale, bias, out);
}